// round 2
// baseline (speedup 1.0000x reference)
#include <cuda_runtime.h>
#include <math.h>
#include <stdint.h>

// Problem constants (fixed by the reference)
#define NHEAD 8
#define NLVL 4
#define NPNT 4
#define BB 4
#define NQ 8000
#define CC 256
#define DH 32
#define STOT 19947   // 100*150 + 50*75 + 25*38 + 13*19

__device__ __constant__ int c_lvlH[NLVL] = {100, 50, 25, 13};
__device__ __constant__ int c_lvlW[NLVL] = {150, 75, 38, 19};
__device__ __constant__ int c_lvlS[NLVL] = {0, 15000, 18750, 19700};

// Scratch (static device globals: allocation-free)
static __device__ float g_value[(size_t)BB * STOT * CC];   // [B,S,NH,DH] = [B,S,C]
static __device__ float g_off  [(size_t)BB * NQ * CC];     // [B,Nq,NH*NL*NP*2]
static __device__ float g_attn [(size_t)BB * NQ * 128];    // [B,Nq,NH*16] logits
static __device__ float g_tout [(size_t)BB * NQ * CC];     // [B,Nq,NH,DH]

// ---------------------------------------------------------------------------
// SGEMM: C[m,n] = sum_k A[m,k] * W[n,k] + bias[n]
// A: [M,K] row-major, W: [N,K] row-major ("NT" — both K-contiguous)
// BM=BN=128, BK=16, 256 threads, 8x8 per thread.
// Requires K % 16 == 0, N % 128 == 0. M arbitrary (guarded).
// ---------------------------------------------------------------------------
__global__ __launch_bounds__(256) void sgemm_nt_bias(
    const float* __restrict__ A, const float* __restrict__ W,
    const float* __restrict__ bias, float* __restrict__ C,
    int M, int N, int K)
{
    __shared__ float As[16][128];
    __shared__ float Ws[16][128];

    const int tid = threadIdx.x;
    const int m0 = blockIdx.x * 128;
    const int n0 = blockIdx.y * 128;
    const int tr = (tid >> 4) << 3;   // 0..120 step 8
    const int tc = (tid & 15) << 3;   // 0..120 step 8

    const int lRow = tid >> 2;        // 0..63
    const int lCol = (tid & 3) << 2;  // 0,4,8,12

    float acc[8][8];
#pragma unroll
    for (int i = 0; i < 8; i++)
#pragma unroll
        for (int j = 0; j < 8; j++) acc[i][j] = 0.f;

    for (int k0 = 0; k0 < K; k0 += 16) {
#pragma unroll
        for (int hh = 0; hh < 2; hh++) {
            int mr = lRow + hh * 64;
            int m = m0 + mr;
            float4 va = make_float4(0.f, 0.f, 0.f, 0.f);
            if (m < M)
                va = *reinterpret_cast<const float4*>(A + (size_t)m * K + k0 + lCol);
            As[lCol + 0][mr] = va.x;
            As[lCol + 1][mr] = va.y;
            As[lCol + 2][mr] = va.z;
            As[lCol + 3][mr] = va.w;

            int n = n0 + mr;   // always < N (N % 128 == 0, grid.y = N/128)
            float4 vw = *reinterpret_cast<const float4*>(W + (size_t)n * K + k0 + lCol);
            Ws[lCol + 0][mr] = vw.x;
            Ws[lCol + 1][mr] = vw.y;
            Ws[lCol + 2][mr] = vw.z;
            Ws[lCol + 3][mr] = vw.w;
        }
        __syncthreads();

#pragma unroll
        for (int kk = 0; kk < 16; kk++) {
            float ra[8], rw[8];
#pragma unroll
            for (int i = 0; i < 8; i++) ra[i] = As[kk][tr + i];
#pragma unroll
            for (int j = 0; j < 8; j++) rw[j] = Ws[kk][tc + j];
#pragma unroll
            for (int i = 0; i < 8; i++)
#pragma unroll
                for (int j = 0; j < 8; j++)
                    acc[i][j] = fmaf(ra[i], rw[j], acc[i][j]);
        }
        __syncthreads();
    }

    float bv[8];
#pragma unroll
    for (int j = 0; j < 8; j++) bv[j] = bias[n0 + tc + j];

#pragma unroll
    for (int i = 0; i < 8; i++) {
        int m = m0 + tr + i;
        if (m >= M) continue;
        float* crow = C + (size_t)m * N + n0 + tc;
#pragma unroll
        for (int j = 0; j < 8; j++) crow[j] = acc[i][j] + bv[j];
    }
}

// ---------------------------------------------------------------------------
// Fused softmax + bilinear sampling + attention reduce.
// One warp per (b, q, h); lane = channel d (DH=32).
// ---------------------------------------------------------------------------
__global__ __launch_bounds__(256) void msda_sampler(
    const float* __restrict__ value,    // [B,S,NH*DH]
    const float* __restrict__ off,      // [B*Nq, 256]
    const float* __restrict__ logits,   // [B*Nq, 128]
    const float* __restrict__ refp,     // [B,Nq,NL,2]
    float* __restrict__ out)            // [B*Nq, NH*DH]
{
    const int gw = (blockIdx.x * blockDim.x + threadIdx.x) >> 5;
    const int lane = threadIdx.x & 31;
    if (gw >= BB * NQ * NHEAD) return;

    const int h  = gw % NHEAD;
    const int bq = gw / NHEAD;      // b*Nq + q
    const int b  = bq / NQ;

    // --- softmax over 16 logits ---
    const float* lg = logits + (size_t)bq * 128 + h * 16;
    float myl = (lane < 16) ? lg[lane] : -1e30f;
    float mx = myl;
#pragma unroll
    for (int o = 16; o >= 1; o >>= 1) mx = fmaxf(mx, __shfl_xor_sync(0xffffffffu, mx, o));
    float e = (lane < 16) ? expf(myl - mx) : 0.f;
    float s = e;
#pragma unroll
    for (int o = 16; o >= 1; o >>= 1) s += __shfl_xor_sync(0xffffffffu, s, o);
    const float inv = 1.f / s;

    // --- gather offsets (32 floats) and reference points (8 floats) ---
    const float offv = off[(size_t)bq * 256 + h * 32 + lane];
    const float* rp = refp + (size_t)bq * (NLVL * 2);
    float rv = (lane < NLVL * 2) ? rp[lane] : 0.f;

    float acc = 0.f;

#pragma unroll
    for (int l = 0; l < NLVL; l++) {
        const int Hd = c_lvlH[l];
        const int Wd = c_lvlW[l];
        const float fH = (float)Hd, fW = (float)Wd;
        const float* vb = value + ((size_t)(b * STOT + c_lvlS[l])) * CC + h * DH + lane;
        const float rx = __shfl_sync(0xffffffffu, rv, l * 2 + 0);
        const float ry = __shfl_sync(0xffffffffu, rv, l * 2 + 1);

#pragma unroll
        for (int p = 0; p < NPNT; p++) {
            const int pi = l * NPNT + p;
            const float ox = __shfl_sync(0xffffffffu, offv, pi * 2 + 0);
            const float oy = __shfl_sync(0xffffffffu, offv, pi * 2 + 1);
            const float aw = __shfl_sync(0xffffffffu, e, pi) * inv;

            // match reference arithmetic order: loc = ref + off/norm; pix = loc*size - 0.5
            const float lx = rx + ox / fW;
            const float ly = ry + oy / fH;
            const float x = lx * fW - 0.5f;
            const float y = ly * fH - 0.5f;

            const float xf = floorf(x), yf = floorf(y);
            const float wx1 = x - xf, wy1 = y - yf;
            const float wx0 = 1.f - wx1, wy0 = 1.f - wy1;
            const int ix0 = (int)xf, iy0 = (int)yf;
            const int ix1 = ix0 + 1, iy1 = iy0 + 1;

            const bool vx0 = (ix0 >= 0) & (ix0 < Wd);
            const bool vx1 = (ix1 >= 0) & (ix1 < Wd);
            const bool vy0 = (iy0 >= 0) & (iy0 < Hd);
            const bool vy1 = (iy1 >= 0) & (iy1 < Hd);

            float v00 = 0.f, v10 = 0.f, v01 = 0.f, v11 = 0.f;
            if (vx0 & vy0) v00 = __ldg(vb + (size_t)(iy0 * Wd + ix0) * CC);
            if (vx1 & vy0) v10 = __ldg(vb + (size_t)(iy0 * Wd + ix1) * CC);
            if (vx0 & vy1) v01 = __ldg(vb + (size_t)(iy1 * Wd + ix0) * CC);
            if (vx1 & vy1) v11 = __ldg(vb + (size_t)(iy1 * Wd + ix1) * CC);

            const float sval = wx0 * wy0 * v00 + wx1 * wy0 * v10
                             + wx0 * wy1 * v01 + wx1 * wy1 * v11;
            acc = fmaf(aw, sval, acc);
        }
    }

    out[(size_t)bq * CC + h * DH + lane] = acc;
}

// ---------------------------------------------------------------------------
// kernel_launch
// ---------------------------------------------------------------------------
extern "C" void kernel_launch(void* const* d_in, const int* in_sizes, int n_in,
                              void* d_out, int out_size)
{
    const float* query        = (const float*)d_in[0];
    const float* value_levels = (const float*)d_in[1];
    const float* refp         = (const float*)d_in[2];
    // d_in[3] = spatial_shapes (int32) — compile-time constants, unused
    const float* W_off  = (const float*)d_in[4];
    const float* b_off  = (const float*)d_in[5];
    const float* W_attn = (const float*)d_in[6];
    const float* b_attn = (const float*)d_in[7];
    const float* W_val  = (const float*)d_in[8];
    const float* b_val  = (const float*)d_in[9];
    const float* W_out  = (const float*)d_in[10];
    const float* b_out  = (const float*)d_in[11];
    float* out = (float*)d_out;

    float *gv, *go, *ga, *gt;
    cudaGetSymbolAddress((void**)&gv, g_value);
    cudaGetSymbolAddress((void**)&go, g_off);
    cudaGetSymbolAddress((void**)&ga, g_attn);
    cudaGetSymbolAddress((void**)&gt, g_tout);

    const int Mv = BB * STOT;   // 79788
    const int Mq = BB * NQ;     // 32000

    // 1) value projection
    sgemm_nt_bias<<<dim3((Mv + 127) / 128, 2), 256>>>(value_levels, W_val, b_val, gv, Mv, 256, 256);
    // 2) sampling offsets
    sgemm_nt_bias<<<dim3((Mq + 127) / 128, 2), 256>>>(query, W_off, b_off, go, Mq, 256, 256);
    // 3) attention logits
    sgemm_nt_bias<<<dim3((Mq + 127) / 128, 1), 256>>>(query, W_attn, b_attn, ga, Mq, 128, 256);
    // 4) fused softmax + bilinear sample + reduce  (256000 warps, 8 warps/block)
    msda_sampler<<<(BB * NQ * NHEAD) / 8, 256>>>(gv, go, ga, refp, gt);
    // 5) output projection
    sgemm_nt_bias<<<dim3((Mq + 127) / 128, 2), 256>>>(gt, W_out, b_out, out, Mq, 256, 256);
}